// round 8
// baseline (speedup 1.0000x reference)
#include <cuda_runtime.h>
#include <math.h>

#define PP   33
#define IMG  256
#define NT   1024
#define ROWS0 17                 // block half 0: rows 0..16 ; half 1: rows 17..32

__device__ __forceinline__ float2 cmul(float2 a, float2 b) {
    return make_float2(fmaf(a.x, b.x, -a.y * b.y), fmaf(a.x, b.y, a.y * b.x));
}

__global__ __launch_bounds__(NT, 2)
void taper_kernel(const float* __restrict__ ref,
                  const float* __restrict__ mov,
                  const int* __restrict__ xp,
                  const int* __restrict__ yp,
                  float* __restrict__ out, int B) {
    __shared__ float  patch[PP][PP + 3];    // 16B-aligned rows
    __shared__ float2 Ts[PP][PP + 1];       // Ts[i][a]
    __shared__ float2 Tt[PP][PP + 1];       // Tt[b][j] = Ts[j][b]
    __shared__ float2 V[ROWS0][PP + 1];     // this block's V rows
    __shared__ float2 Abase[PP];            // e^{-2pi i (n_q+1)/479}
    __shared__ float2 Ccol[PP];             // e^{-2pi i as/479}
    __shared__ float  W0[PP], W1[PP];       // 479*(1-f_q), 479*f_q

    int blk  = blockIdx.x;
    int ib   = blk >> 1;                    // image index (0..2B-1)
    int half = blk & 1;
    int rowbase = half ? ROWS0 : 0;
    int nrows   = half ? (PP - ROWS0) : ROWS0;

    const float* img;
    float2* o;
    if (ib < B) {
        img = ref + (size_t)ib * IMG * IMG;
        o   = (float2*)out + (size_t)ib * PP * PP;
    } else {
        img = mov + (size_t)(ib - B) * IMG * IMG;
        o   = (float2*)out + (size_t)B * PP * PP + (size_t)(ib - B) * PP * PP;
    }
    int x0 = xp ? __ldg(xp) : 100;
    int y0 = yp ? __ldg(yp) : 50;

    int tid = threadIdx.x;

    // ---- Phase A0: only 66 transcendental calls per block (MUFU ~ free);
    //      all threads stage the patch (LDG latency overlaps).
    if (tid < PP) {
        int q = tid;
        int ii = q + 16; if (ii >= PP) ii -= PP;    // undo ifftshift
        int n16 = 478 * ii;                          // c = ii*478/32 exact
        int n = n16 >> 5;
        float f = (float)(n16 & 31) * 0.03125f;
        float s, c;
        sincospif((float)(-2 * (n + 1)) * (1.0f / 479.0f), &s, &c);
        Abase[q] = make_float2(c, s);
        W0[q] = 479.0f * (1.0f - f);
        W1[q] = 479.0f * f;
    } else if (tid < 2 * PP) {
        int r = tid - PP;
        float s, c;
        sincospif((float)(-2 * (r - 16)) * (1.0f / 479.0f), &s, &c);
        Ccol[r] = make_float2(c, s);
    }
    for (int idx = tid; idx < PP * PP; idx += NT) {
        int q = idx / PP, r = idx - q * PP;
        patch[q][r] = img[(size_t)(x0 + q) * IMG + (y0 + r)];
    }
    __syncthreads();

    // ---- Phase A1: T[q][r] = (W0+W1*C[r]) * Abase[q]^{as}, square-and-multiply
    //      (all FMA-pipe work; ~40 instrs per element, 1089 elements).
    for (int idx = tid; idx < PP * PP; idx += NT) {
        int q = idx / PP, r = idx - q * PP;
        int as = r - 16;
        unsigned u = (unsigned)(as < 0 ? -as : as);
        float2 base = Abase[q];
        float2 res = make_float2(1.0f, 0.0f);
#pragma unroll
        for (int k = 0; k < 5; k++) {
            float2 rm = cmul(res, base);
            if ((u >> k) & 1u) res = rm;
            base = cmul(base, base);
        }
        if (as < 0) res.y = -res.y;
        float2 C = Ccol[r];
        float w0 = W0[q], w1 = W1[q];
        float2 pre = make_float2(fmaf(w1, C.x, w0), w1 * C.y);
        float2 t = cmul(pre, res);
        Ts[q][r] = t;
        Tt[r][q] = t;
    }
    __syncthreads();

    int nwork = nrows * PP;    // 561 or 528 — one iteration per thread, no tail

    // ---- Stage 1: V[i][b] = sum_a Ts[i][a] * patch[a][b]   (complex x real)
    if (tid < nwork) {
        int li = tid / PP;
        int bb = tid - li * PP;
        int i  = rowbase + li;
        const float4* trow = reinterpret_cast<const float4*>(Ts[i]);
        float rx = 0.f, ry = 0.f, rx2 = 0.f, ry2 = 0.f;
#pragma unroll
        for (int h = 0; h < 16; h++) {
            float4 tv = trow[h];
            float p0 = patch[2 * h][bb];
            float p1 = patch[2 * h + 1][bb];
            rx  = fmaf(tv.x, p0, rx);
            ry  = fmaf(tv.y, p0, ry);
            rx2 = fmaf(tv.z, p1, rx2);
            ry2 = fmaf(tv.w, p1, ry2);
        }
        float2 tl = Ts[i][32];
        float  pl = patch[32][bb];
        V[li][bb] = make_float2(fmaf(tl.x, pl, rx + rx2),
                                fmaf(tl.y, pl, ry + ry2));
    }
    __syncthreads();

    // ---- Stage 2: out[i][j] = sum_b V[i][b] * Tt[b][j]   (complex x complex)
    if (tid < nwork) {
        int li = tid / PP;
        int j  = tid - li * PP;
        int i  = rowbase + li;
        const float4* vrow = reinterpret_cast<const float4*>(V[li]);
        float rxx = 0.f, ryy = 0.f, rxy = 0.f, ryx = 0.f;
#pragma unroll
        for (int h = 0; h < 16; h++) {
            float4 vv = vrow[h];
            float2 t0 = Tt[2 * h][j];
            float2 t1 = Tt[2 * h + 1][j];
            rxx = fmaf(vv.x, t0.x, rxx);
            ryy = fmaf(vv.y, t0.y, ryy);
            rxy = fmaf(vv.x, t0.y, rxy);
            ryx = fmaf(vv.y, t0.x, ryx);
            rxx = fmaf(vv.z, t1.x, rxx);
            ryy = fmaf(vv.w, t1.y, ryy);
            rxy = fmaf(vv.z, t1.y, rxy);
            ryx = fmaf(vv.w, t1.x, ryx);
        }
        float2 vl = V[li][32];
        float2 tl = Tt[32][j];
        rxx = fmaf(vl.x, tl.x, rxx);
        ryy = fmaf(vl.y, tl.y, ryy);
        rxy = fmaf(vl.x, tl.y, rxy);
        ryx = fmaf(vl.y, tl.x, ryx);
        o[(size_t)i * PP + j] = make_float2(rxx - ryy, rxy + ryx);
    }
}

extern "C" void kernel_launch(void* const* d_in, const int* in_sizes, int n_in,
                              void* d_out, int out_size) {
    const float* ref = (const float*)d_in[0];
    const float* mov = (const float*)d_in[1];
    const int* xp = (n_in > 2) ? (const int*)d_in[2] : nullptr;
    const int* yp = (n_in > 3) ? (const int*)d_in[3] : nullptr;
    float* out = (float*)d_out;
    int B = in_sizes[0] / (IMG * IMG);

    taper_kernel<<<4 * B, NT>>>(ref, mov, xp, yp, out, B);
}

// round 9
// speedup vs baseline: 1.1866x; 1.1866x over previous
#include <cuda_runtime.h>
#include <math.h>

#define PP   33
#define IMG  256
#define NT   1024
#define ROWS0 17                 // block half 0: rows 0..16 ; half 1: rows 17..32
#define NPAIR (PP * 17)          // 561 pair-items

__global__ __launch_bounds__(NT, 2)
void taper_kernel(const float* __restrict__ ref,
                  const float* __restrict__ mov,
                  const int* __restrict__ xp,
                  const int* __restrict__ yp,
                  float* __restrict__ out, int B) {
    __shared__ float  patch[PP][PP + 3];    // 16B-aligned rows
    __shared__ float2 Ts[PP][PP + 1];       // Ts[i][a]
    __shared__ float2 Tt[PP][PP + 1];       // Tt[b][j] = Ts[j][b]
    __shared__ float2 V[ROWS0][PP + 1];     // this block's V rows

    int blk  = blockIdx.x;
    int ib   = blk >> 1;                    // image index (0..2B-1)
    int half = blk & 1;
    int rowbase = half ? ROWS0 : 0;
    int nrows   = half ? (PP - ROWS0) : ROWS0;

    const float* img;
    float2* o;
    if (ib < B) {
        img = ref + (size_t)ib * IMG * IMG;
        o   = (float2*)out + (size_t)ib * PP * PP;
    } else {
        img = mov + (size_t)(ib - B) * IMG * IMG;
        o   = (float2*)out + (size_t)B * PP * PP + (size_t)(ib - B) * PP * PP;
    }

    int tid = threadIdx.x;

    // Kick off xp/yp loads immediately (long-latency, block-critical).
    int x0 = xp ? __ldg(xp) : 100;
    int y0 = yp ? __ldg(yp) : 50;

    // Speculative L2 prefetch of the patch at the expected position (100,50).
    // Independent of x0 -> issues before xp returns. Harmless if guess is wrong.
    if (tid < PP * PP) {
        int q = tid / PP, r = tid - q * PP;
        const float* g = img + (size_t)(100 + q) * IMG + (50 + r);
        asm volatile("prefetch.global.L2 [%0];" :: "l"(g));
    }

    // ---- Phase A-trig (x0-independent; overlaps the xp latency):
    //      conjugate pairs: T[q][32-r] = conj(T[q][r]) -> 561 items, 2 sincospif each.
    if (tid < NPAIR) {
        int q  = tid / 17;
        int rp = tid - q * 17;               // 0..16 -> columns rp and 32-rp

        int ii  = q + 16; if (ii >= PP) ii -= PP;   // undo ifftshift
        int n16 = 478 * ii;                          // c = ii*478/32 exactly
        int n   = n16 >> 5;
        float f = (float)(n16 & 31) * 0.03125f;
        int as  = rp - 16;                           // in [-16, 0]
        float s1, c1, s2, c2;
        sincospif((float)(-2 * as * (n + 1)) * (1.0f / 479.0f), &s1, &c1);
        sincospif((float)(-2 * as * (n + 2)) * (1.0f / 479.0f), &s2, &c2);
        float w0 = 479.0f * (1.0f - f), w1 = 479.0f * f;
        float tre = fmaf(w0, c1, w1 * c2);
        float tim = fmaf(w0, s1, w1 * s2);
        float2 t  = make_float2(tre,  tim);
        float2 tc = make_float2(tre, -tim);          // conj for mirrored column
        int rm = 32 - rp;
        Ts[q][rp] = t;   Tt[rp][q] = t;
        Ts[q][rm] = tc;  Tt[rm][q] = tc;             // rp==16 double-writes same value
    }

    // ---- Phase A-load: stage the patch (hits L2 thanks to the prefetch).
    {
        int q = tid / PP, r = tid - q * PP;          // tid 0..1023 covers idx 0..1023
        patch[q][r] = img[(size_t)(x0 + q) * IMG + (y0 + r)];
        if (tid >= NT - 65) {                        // warps 29-31 take the 65-item tail
            int idx = 1024 + (NT - 1 - tid);         // 1024..1088
            int q2 = idx / PP, r2 = idx - q2 * PP;
            patch[q2][r2] = img[(size_t)(x0 + q2) * IMG + (y0 + r2)];
        }
    }
    __syncthreads();

    int nwork = nrows * PP;    // 561 or 528 — one iteration per thread, no tail

    // ---- Stage 1: V[i][b] = sum_a Ts[i][a] * patch[a][b]   (complex x real)
    if (tid < nwork) {
        int li = tid / PP;
        int bb = tid - li * PP;
        int i  = rowbase + li;
        const float4* trow = reinterpret_cast<const float4*>(Ts[i]);
        float rx = 0.f, ry = 0.f, rx2 = 0.f, ry2 = 0.f;
#pragma unroll
        for (int h = 0; h < 16; h++) {
            float4 tv = trow[h];
            float p0 = patch[2 * h][bb];
            float p1 = patch[2 * h + 1][bb];
            rx  = fmaf(tv.x, p0, rx);
            ry  = fmaf(tv.y, p0, ry);
            rx2 = fmaf(tv.z, p1, rx2);
            ry2 = fmaf(tv.w, p1, ry2);
        }
        float2 tl = Ts[i][32];
        float  pl = patch[32][bb];
        V[li][bb] = make_float2(fmaf(tl.x, pl, rx + rx2),
                                fmaf(tl.y, pl, ry + ry2));
    }
    __syncthreads();

    // ---- Stage 2: out[i][j] = sum_b V[i][b] * Tt[b][j]   (complex x complex)
    if (tid < nwork) {
        int li = tid / PP;
        int j  = tid - li * PP;
        int i  = rowbase + li;
        const float4* vrow = reinterpret_cast<const float4*>(V[li]);
        float rxx = 0.f, ryy = 0.f, rxy = 0.f, ryx = 0.f;
#pragma unroll
        for (int h = 0; h < 16; h++) {
            float4 vv = vrow[h];
            float2 t0 = Tt[2 * h][j];
            float2 t1 = Tt[2 * h + 1][j];
            rxx = fmaf(vv.x, t0.x, rxx);
            ryy = fmaf(vv.y, t0.y, ryy);
            rxy = fmaf(vv.x, t0.y, rxy);
            ryx = fmaf(vv.y, t0.x, ryx);
            rxx = fmaf(vv.z, t1.x, rxx);
            ryy = fmaf(vv.w, t1.y, ryy);
            rxy = fmaf(vv.z, t1.y, rxy);
            ryx = fmaf(vv.w, t1.x, ryx);
        }
        float2 vl = V[li][32];
        float2 tl = Tt[32][j];
        rxx = fmaf(vl.x, tl.x, rxx);
        ryy = fmaf(vl.y, tl.y, ryy);
        rxy = fmaf(vl.x, tl.y, rxy);
        ryx = fmaf(vl.y, tl.x, ryx);
        o[(size_t)i * PP + j] = make_float2(rxx - ryy, rxy + ryx);
    }
}

extern "C" void kernel_launch(void* const* d_in, const int* in_sizes, int n_in,
                              void* d_out, int out_size) {
    const float* ref = (const float*)d_in[0];
    const float* mov = (const float*)d_in[1];
    const int* xp = (n_in > 2) ? (const int*)d_in[2] : nullptr;
    const int* yp = (n_in > 3) ? (const int*)d_in[3] : nullptr;
    float* out = (float*)d_out;
    int B = in_sizes[0] / (IMG * IMG);

    taper_kernel<<<4 * B, NT>>>(ref, mov, xp, yp, out, B);
}

// round 10
// speedup vs baseline: 1.2149x; 1.0239x over previous
#include <cuda_runtime.h>
#include <math.h>

#define PP    33
#define IMG   256
#define NT    1024
#define ROWS0 17                 // half 0: rows 0..16 ; half 1: rows 17..32
#define NPAIR (PP * 17)          // 561

__global__ __launch_bounds__(NT, 2)
void taper_kernel(const float* __restrict__ ref,
                  const float* __restrict__ mov,
                  const int* __restrict__ xp,
                  const int* __restrict__ yp,
                  float* __restrict__ out, int B) {
    __shared__ float  PS[17][36];           // p[a]+p[32-a] (a<=16; PS[16]=p16)
    __shared__ float  PD[17][36];           // p[a]-p[32-a] (PD[16]=0)
    __shared__ float2 Ts17[PP][18];         // Ts17[i][a], a<=16 (row-uniform reads)
    __shared__ float2 Tt17[17][PP + 1];     // Tt17[b][j]=Ts[j][b], b<=16 (lane reads)
    __shared__ float2 V[ROWS0][PP + 1];     // V rows for this block
    __shared__ float4 SD[ROWS0][16];        // (s.x,s.y,d.x,d.y) per (row, bpair)

    int blk  = blockIdx.x;
    int ib   = blk >> 1;
    int half = blk & 1;
    int rowbase = half ? ROWS0 : 0;
    int nrows   = half ? (PP - ROWS0) : ROWS0;

    const float* img;
    float2* o;
    if (ib < B) {
        img = ref + (size_t)ib * IMG * IMG;
        o   = (float2*)out + (size_t)ib * PP * PP;
    } else {
        img = mov + (size_t)(ib - B) * IMG * IMG;
        o   = (float2*)out + (size_t)B * PP * PP + (size_t)(ib - B) * PP * PP;
    }

    int tid = threadIdx.x;

    int x0 = xp ? __ldg(xp) : 100;
    int y0 = yp ? __ldg(yp) : 50;

    // Speculative L2 prefetch at the expected position (harmless if wrong).
    if (tid < PP * PP) {
        int q = tid / PP, r = tid - q * PP;
        const float* g = img + (size_t)(100 + q) * IMG + (50 + r);
        asm volatile("prefetch.global.L2 [%0];" :: "l"(g));
    }

    // ---- Phase A (561 active threads): patch row-pair -> PS/PD, and pair-trig T.
    if (tid < NPAIR) {
        // patch pairs: qp = row 0..16 paired with 32-qp
        int qp = tid / PP;
        int r  = tid - qp * PP;
        float pa = img[(size_t)(x0 + qp) * IMG + (y0 + r)];
        float pm = img[(size_t)(x0 + 32 - qp) * IMG + (y0 + r)];
        if (qp == 16) { PS[16][r] = pa; PD[16][r] = 0.0f; }
        else          { PS[qp][r] = pa + pm; PD[qp][r] = pa - pm; }

        // trig pairs: columns rp<=16 of row q (T[q][32-rp] = conj(T[q][rp]))
        int q  = tid % PP;
        int rp = tid / PP;                   // 0..16
        int ii  = q + 16; if (ii >= PP) ii -= PP;
        int n16 = 478 * ii;
        int n   = n16 >> 5;
        float f = (float)(n16 & 31) * 0.03125f;
        int as  = rp - 16;                   // in [-16, 0]
        float s1, c1, s2, c2;
        sincospif((float)(-2 * as * (n + 1)) * (1.0f / 479.0f), &s1, &c1);
        sincospif((float)(-2 * as * (n + 2)) * (1.0f / 479.0f), &s2, &c2);
        float w0 = 479.0f * (1.0f - f), w1 = 479.0f * f;
        float2 t = make_float2(fmaf(w0, c1, w1 * c2), fmaf(w0, s1, w1 * s2));
        Ts17[q][rp] = t;
        Tt17[rp][q] = t;
    }
    __syncthreads();

    int nwork = nrows * PP;      // 561 or 528

    // ---- Stage 1: V[i][b] (34 fma via a-pair symmetry)
    if (tid < nwork) {
        int li = tid / PP;
        int bb = tid - li * PP;
        int i  = rowbase + li;
        const float4* trow = reinterpret_cast<const float4*>(Ts17[i]);
        float vx = 0.f, vy = 0.f, vx2 = 0.f, vy2 = 0.f;
#pragma unroll
        for (int h = 0; h < 8; h++) {
            float4 tv = trow[h];             // Ts17[i][2h], Ts17[i][2h+1] (uniform)
            vx  = fmaf(tv.x, PS[2 * h][bb], vx);
            vy  = fmaf(tv.y, PD[2 * h][bb], vy);
            vx2 = fmaf(tv.z, PS[2 * h + 1][bb], vx2);
            vy2 = fmaf(tv.w, PD[2 * h + 1][bb], vy2);
        }
        float2 tl = Ts17[i][16];             // t.y == 0 (as = 0)
        V[li][bb] = make_float2(fmaf(tl.x, PS[16][bb], vx + vx2),
                                vy + vy2);
    }
    __syncthreads();

    // ---- s/d phase: SD[li][bp] = (V[li][bp]+V[li][32-bp], V[li][bp]-V[li][32-bp])
    if (tid < nrows * 16) {
        int li = tid >> 4;
        int bp = tid & 15;
        float2 vb = V[li][bp];
        float2 vm = V[li][32 - bp];
        SD[li][bp] = make_float4(vb.x + vm.x, vb.y + vm.y,
                                 vb.x - vm.x, vb.y - vm.y);
    }
    __syncthreads();

    // ---- Stage 2: out[i][j] (68 fma via b-pair symmetry)
    if (tid < nwork) {
        int li = tid / PP;
        int j  = tid - li * PP;
        int i  = rowbase + li;
        float re = 0.f, im = 0.f, re2 = 0.f, im2 = 0.f;
#pragma unroll
        for (int bp = 0; bp < 16; bp += 2) {
            float4 sd0 = SD[li][bp];         // uniform
            float4 sd1 = SD[li][bp + 1];
            float2 t0  = Tt17[bp][j];        // lane stride-1
            float2 t1  = Tt17[bp + 1][j];
            re  = fmaf(t0.x, sd0.x, re);   re  = fmaf(-t0.y, sd0.w, re);
            im  = fmaf(t0.x, sd0.y, im);   im  = fmaf( t0.y, sd0.z, im);
            re2 = fmaf(t1.x, sd1.x, re2);  re2 = fmaf(-t1.y, sd1.w, re2);
            im2 = fmaf(t1.x, sd1.y, im2);  im2 = fmaf( t1.y, sd1.z, im2);
        }
        // center b = 16: t.y == 0
        float2 vc = V[li][16];
        float2 tc = Tt17[16][j];
        re = fmaf(vc.x, tc.x, re + re2);
        im = fmaf(vc.y, tc.x, im + im2);
        o[(size_t)i * PP + j] = make_float2(re, im);
    }
}

extern "C" void kernel_launch(void* const* d_in, const int* in_sizes, int n_in,
                              void* d_out, int out_size) {
    const float* ref = (const float*)d_in[0];
    const float* mov = (const float*)d_in[1];
    const int* xp = (n_in > 2) ? (const int*)d_in[2] : nullptr;
    const int* yp = (n_in > 3) ? (const int*)d_in[3] : nullptr;
    float* out = (float*)d_out;
    int B = in_sizes[0] / (IMG * IMG);

    taper_kernel<<<4 * B, NT>>>(ref, mov, xp, yp, out, B);
}